// round 1
// baseline (speedup 1.0000x reference)
#include <cuda_runtime.h>

typedef unsigned long long u64;

__device__ __forceinline__ u64 pk2(float lo, float hi) {
    u64 r; asm("mov.b64 %0, {%1, %2};" : "=l"(r) : "f"(lo), "f"(hi)); return r;
}
__device__ __forceinline__ u64 dup2(float v) { return pk2(v, v); }
__device__ __forceinline__ void upk2(u64 v, float& a, float& b) {
    asm("mov.b64 {%0, %1}, %2;" : "=f"(a), "=f"(b) : "l"(v));
}
// Packed f32x2 FMA (Blackwell FFMA2) — 2x fp32 throughput per issue slot.
__device__ __forceinline__ u64 fma2(u64 a, u64 b, u64 c) {
    u64 d; asm("fma.rn.f32x2 %0, %1, %2, %3;" : "=l"(d) : "l"(a), "l"(b), "l"(c)); return d;
}

#define KNN 9
#define CC 256      // channels
#define CF 16       // reduced channels
#define NN 256      // nodes per patch (16x16)
#define HW 12544    // 112*112

__global__ __launch_bounds__(256) void gnn_fused_kernel(
    const float* __restrict__ x,
    const float* __restrict__ f_w, const float* __restrict__ f_b,
    const float* __restrict__ p_w, const float* __restrict__ p_b,
    const float* __restrict__ e_a, const float* __restrict__ e_b,
    float* __restrict__ out)
{
    // w2: holds cf-pair-packed f_w during phase 1, then cf-pair-packed p_w for phase 3.
    __shared__ ulonglong2 w2[256][4];       // 16 KB
    __shared__ ulonglong2 nodes2[256][4];   // 16 KB: [node][cf-pairs packed]
    __shared__ float nrm_s[256];
    __shared__ float pb_s[256];

    const int t   = threadIdx.x;
    const int blk = blockIdx.x;
    const int b   = blk / 49;
    const int rr  = blk % 49;
    const int wgi = rr / 7, wgj = rr % 7;
    const int wi  = t >> 4, hj = t & 15;   // node = wi*16 + hj

    // ---- load fw2[c][j] = (f_w[2j][c], f_w[2j+1][c]) ----
    {
        u64* w = (u64*)w2;
        #pragma unroll
        for (int i = 0; i < 8; ++i) {
            int idx = i * 256 + t;
            int c = idx >> 3, j = idx & 7;
            w[idx] = pk2(f_w[(2 * j) * CC + c], f_w[(2 * j + 1) * CC + c]);
        }
    }
    pb_s[t] = p_b[t];

    u64 acc2[8];
    #pragma unroll
    for (int j = 0; j < 8; ++j) acc2[j] = pk2(f_b[2 * j], f_b[2 * j + 1]);

    __syncthreads();

    // ---- Phase 1: f conv (C=256 -> Cf=16), thread t = pixel t ----
    const float* xp = x + (size_t)b * CC * HW
                        + (size_t)((wgi * 16 + wi) * 112 + wgj * 16 + hj);
    #pragma unroll 1
    for (int c0 = 0; c0 < CC; c0 += 8) {
        float xv[8];
        #pragma unroll
        for (int u = 0; u < 8; ++u) xv[u] = xp[(size_t)(c0 + u) * HW];
        #pragma unroll
        for (int u = 0; u < 8; ++u) {
            u64 xx = dup2(xv[u]);
            #pragma unroll
            for (int j2 = 0; j2 < 4; ++j2) {
                ulonglong2 q = w2[c0 + u][j2];
                acc2[2 * j2]     = fma2(xx, q.x, acc2[2 * j2]);
                acc2[2 * j2 + 1] = fma2(xx, q.y, acc2[2 * j2 + 1]);
            }
        }
    }

    // ---- node norm ----
    u64 s2 = 0ull;
    #pragma unroll
    for (int j = 0; j < 8; ++j) s2 = fma2(acc2[j], acc2[j], s2);
    float sqa, sqb; upk2(s2, sqa, sqb);
    const float nrm = sqrtf(sqa + sqb);

    __syncthreads();   // all reads of w2 (f_w) done before overwrite

    // stage nodes + norms; reload w2 with pw2[co][j] = (p_w[co][2j], p_w[co][2j+1])
    #pragma unroll
    for (int j2 = 0; j2 < 4; ++j2) {
        ulonglong2 q; q.x = acc2[2 * j2]; q.y = acc2[2 * j2 + 1];
        nodes2[t][j2] = q;
    }
    nrm_s[t] = nrm;
    {
        u64* w = (u64*)w2;
        #pragma unroll
        for (int i = 0; i < 8; ++i) {
            int idx = i * 256 + t;
            int co = idx >> 3, j = idx & 7;
            w[idx] = pk2(p_w[co * CF + 2 * j], p_w[co * CF + 2 * j + 1]);
        }
    }
    __syncthreads();

    // ---- Phase 2: cosine sim row + running top-9 (register sorted, stable) ----
    const float alpha = e_a[0], beta = e_b[0];
    float bv[KNN]; int bi[KNN];
    #pragma unroll
    for (int k = 0; k < KNN; ++k) { bv[k] = -3.4e38f; bi[k] = 0; }

    #pragma unroll 2
    for (int m = 0; m < NN; ++m) {
        u64 da = 0ull, db = 0ull;
        #pragma unroll
        for (int j2 = 0; j2 < 4; ++j2) {
            ulonglong2 q = nodes2[m][j2];   // broadcast across warp
            da = fma2(acc2[2 * j2],     q.x, da);
            db = fma2(acc2[2 * j2 + 1], q.y, db);
        }
        float a0, a1, b0, b1; upk2(da, a0, a1); upk2(db, b0, b1);
        float dot = (a0 + a1) + (b0 + b1);
        float den = fmaxf(nrm * nrm_s[m], 1e-8f);
        float sim = __fdividef(dot, den);
        if (sim > bv[KNN - 1]) {
            bv[KNN - 1] = sim; bi[KNN - 1] = m;
            #pragma unroll
            for (int j = KNN - 1; j > 0; --j) {
                if (bv[j] > bv[j - 1]) {
                    float tv = bv[j]; bv[j] = bv[j - 1]; bv[j - 1] = tv;
                    int   ti = bi[j]; bi[j] = bi[j - 1]; bi[j - 1] = ti;
                }
            }
        }
    }

    // ---- edge weights + normalized gather ----
    float wn[KNN]; float wsum = 0.f;
    #pragma unroll
    for (int k = 0; k < KNN; ++k) {
        float e = __expf(-(beta + alpha * bv[k]));
        wn[k] = __fdividef(1.f, 1.f + e);
        wsum += wn[k];
    }
    const float inv = __fdividef(1.f, wsum + 1e-12f);

    u64 o2[8];
    #pragma unroll
    for (int j = 0; j < 8; ++j) o2[j] = 0ull;
    #pragma unroll
    for (int k = 0; k < KNN; ++k) {
        u64 ww = dup2(wn[k] * inv);
        #pragma unroll
        for (int j2 = 0; j2 < 4; ++j2) {
            ulonglong2 q = nodes2[bi[k]][j2];
            o2[2 * j2]     = fma2(ww, q.x, o2[2 * j2]);
            o2[2 * j2 + 1] = fma2(ww, q.y, o2[2 * j2 + 1]);
        }
    }

    // ---- Phase 3: p conv (Cf=16 -> C=256) + store; mirrors input access pattern ----
    float* op = out + (size_t)b * CC * HW
                    + (size_t)((wgi * 16 + wi) * 112 + wgj * 16 + hj);
    #pragma unroll 4
    for (int co = 0; co < CC; ++co) {
        u64 sa2 = 0ull, sb2 = 0ull;
        #pragma unroll
        for (int j2 = 0; j2 < 4; ++j2) {
            ulonglong2 q = w2[co][j2];      // broadcast
            sa2 = fma2(q.x, o2[2 * j2],     sa2);
            sb2 = fma2(q.y, o2[2 * j2 + 1], sb2);
        }
        float p0, p1, p2, p3; upk2(sa2, p0, p1); upk2(sb2, p2, p3);
        op[(size_t)co * HW] = (p0 + p1) + (p2 + p3) + pb_s[co];
    }
}

extern "C" void kernel_launch(void* const* d_in, const int* in_sizes, int n_in,
                              void* d_out, int out_size) {
    const float* x   = (const float*)d_in[0];
    const float* f_w = (const float*)d_in[1];
    const float* f_b = (const float*)d_in[2];
    const float* p_w = (const float*)d_in[3];
    const float* p_b = (const float*)d_in[4];
    const float* e_a = (const float*)d_in[5];
    const float* e_b = (const float*)d_in[6];
    float* out = (float*)d_out;
    gnn_fused_kernel<<<784, 256>>>(x, f_w, f_b, p_w, p_b, e_a, e_b, out);
}

// round 2
// speedup vs baseline: 1.5496x; 1.5496x over previous
#include <cuda_runtime.h>

typedef unsigned long long u64;
typedef unsigned int u32;

__device__ __forceinline__ u64 pk2(float lo, float hi) {
    u64 r; asm("mov.b64 %0, {%1, %2};" : "=l"(r) : "f"(lo), "f"(hi)); return r;
}
__device__ __forceinline__ u64 dup2(float v) { return pk2(v, v); }
__device__ __forceinline__ void upk2(u64 v, float& a, float& b) {
    asm("mov.b64 {%0, %1}, %2;" : "=f"(a), "=f"(b) : "l"(v));
}
// Packed f32x2 ops (Blackwell) — 2x fp32 per issue slot.
__device__ __forceinline__ u64 fma2(u64 a, u64 b, u64 c) {
    u64 d; asm("fma.rn.f32x2 %0, %1, %2, %3;" : "=l"(d) : "l"(a), "l"(b), "l"(c)); return d;
}
__device__ __forceinline__ u64 add2(u64 a, u64 b) {
    u64 d; asm("add.rn.f32x2 %0, %1, %2;" : "=l"(d) : "l"(a), "l"(b)); return d;
}
__device__ __forceinline__ u64 mul2(u64 a, u64 b) {
    u64 d; asm("mul.rn.f32x2 %0, %1, %2;" : "=l"(d) : "l"(a), "l"(b)); return d;
}

#define KNN 9
#define CC 256      // channels
#define NN 256      // nodes per patch (16x16)
#define HW 12544    // 112*112

__global__ __launch_bounds__(256) void gnn_fused_kernel(
    const float* __restrict__ x,
    const float* __restrict__ f_w, const float* __restrict__ f_b,
    const float* __restrict__ p_w, const float* __restrict__ p_b,
    const float* __restrict__ e_a, const float* __restrict__ e_b,
    float* __restrict__ out)
{
    // wbuf: phase 1 = fw2[c][j2] (cf-pair packed f_w), phase 3 = w3[copair][u].
    __shared__ ulonglong2 wbuf[256][4];     // 16 KB
    __shared__ ulonglong2 nodes2[256][4];   // 16 KB: normalized node features
    __shared__ float nrm_s[256];
    __shared__ u64 pb2_s[128];              // packed (p_b[2cp], p_b[2cp+1])

    const int t   = threadIdx.x;
    const int blk = blockIdx.x;
    const int b   = blk / 49;
    const int rr  = blk % 49;
    const int wgi = rr / 7, wgj = rr % 7;
    const int wi  = t >> 4, hj = t & 15;   // node = wi*16 + hj

    // ---- build fw2[c][j] = (f_w[2j][c], f_w[2j+1][c]) ----
    {
        u64* w = (u64*)wbuf;
        #pragma unroll
        for (int i = 0; i < 8; ++i) {
            int idx = i * 256 + t;
            int c = idx >> 3, j = idx & 7;
            w[idx] = pk2(f_w[(2 * j) * CC + c], f_w[(2 * j + 1) * CC + c]);
        }
    }

    u64 acc2[8];
    #pragma unroll
    for (int j = 0; j < 8; ++j) acc2[j] = pk2(f_b[2 * j], f_b[2 * j + 1]);

    __syncthreads();

    // ---- Phase 1: f conv (C=256 -> Cf=16), thread t = pixel t ----
    const float* xp = x + (size_t)b * CC * HW
                        + (size_t)((wgi * 16 + wi) * 112 + wgj * 16 + hj);
    #pragma unroll 1
    for (int c0 = 0; c0 < CC; c0 += 8) {
        float xv[8];
        #pragma unroll
        for (int u = 0; u < 8; ++u) xv[u] = xp[(size_t)u * HW];
        xp += (size_t)8 * HW;
        #pragma unroll
        for (int u = 0; u < 8; ++u) {
            u64 xx = dup2(xv[u]);
            #pragma unroll
            for (int j2 = 0; j2 < 4; ++j2) {
                ulonglong2 q = wbuf[c0 + u][j2];
                acc2[2 * j2]     = fma2(xx, q.x, acc2[2 * j2]);
                acc2[2 * j2 + 1] = fma2(xx, q.y, acc2[2 * j2 + 1]);
            }
        }
    }

    // ---- normalize node in registers (kills per-m div/max/mul in phase 2) ----
    u64 s2 = 0ull;
    #pragma unroll
    for (int j = 0; j < 8; ++j) s2 = fma2(acc2[j], acc2[j], s2);
    float sqa, sqb; upk2(s2, sqa, sqb);
    const float ss  = sqa + sqb;
    const float nrm = sqrtf(ss);
    const float rinv = rsqrtf(fmaxf(ss, 1e-24f));
    {
        u64 rv = dup2(rinv);
        #pragma unroll
        for (int j = 0; j < 8; ++j) acc2[j] = mul2(acc2[j], rv);
    }
    // stage normalized nodes + norms
    #pragma unroll
    for (int j2 = 0; j2 < 4; ++j2) {
        ulonglong2 q; q.x = acc2[2 * j2]; q.y = acc2[2 * j2 + 1];
        nodes2[t][j2] = q;
    }
    nrm_s[t] = nrm;

    __syncthreads();   // phase-1 reads of wbuf done; nodes2 visible

    // ---- rebuild wbuf as w3[cp][u]: lanes = (co=2cp, co+1) weight pairs ----
    {
        const float2* pw2 = (const float2*)p_w;   // p_w is [256][16]
        ulonglong2* w = (ulonglong2*)wbuf;
        #pragma unroll
        for (int i = 0; i < 4; ++i) {
            int e = i * 256 + t;
            int cp = e >> 3, uu = e & 7;
            float2 a = pw2[cp * 16 + uu];       // row 2cp,   cols 2u,2u+1
            float2 bb = pw2[cp * 16 + 8 + uu];  // row 2cp+1, cols 2u,2u+1
            ulonglong2 q;
            q.x = pk2(a.x, bb.x);
            q.y = pk2(a.y, bb.y);
            w[e] = q;
        }
        if (t < 128) {
            float2 pb = ((const float2*)p_b)[t];
            pb2_s[t] = pk2(pb.x, pb.y);
        }
    }
    __syncthreads();

    // ---- Phase 2: cosine sim + branch-free top-9 via packed u32 keys ----
    // key = (bits(clamp(dot,-1)+2) - 0x3F800000) * 256 + m : exact fp32 order,
    // index in low 8 bits, unconditional 17-IMNMX sorted insert.
    u32 bv[KNN];
    #pragma unroll
    for (int k = 0; k < KNN; ++k) bv[k] = 0u;

    #pragma unroll 4
    for (int m = 0; m < NN; ++m) {
        ulonglong2 q0 = nodes2[m][0];
        ulonglong2 q1 = nodes2[m][1];
        ulonglong2 q2 = nodes2[m][2];
        ulonglong2 q3 = nodes2[m][3];
        u64 da = mul2(acc2[0], q0.x);
        u64 db = mul2(acc2[1], q0.y);
        da = fma2(acc2[2], q1.x, da);
        db = fma2(acc2[3], q1.y, db);
        da = fma2(acc2[4], q2.x, da);
        db = fma2(acc2[5], q2.y, db);
        da = fma2(acc2[6], q3.x, da);
        db = fma2(acc2[7], q3.y, db);
        u64 dd = add2(da, db);
        float d0, d1; upk2(dd, d0, d1);
        float dot = d0 + d1;
        float tt = fmaxf(dot, -1.0f) + 2.0f;          // tt in [1, ~3)
        u32 u = __float_as_uint(tt) - 0x3F800000u;    // 24-bit monotonic
        u32 key = u * 256u + (u32)m;
        bv[KNN - 1] = max(bv[KNN - 1], key);
        #pragma unroll
        for (int j = KNN - 1; j > 0; --j) {
            u32 lo = min(bv[j], bv[j - 1]);
            u32 hi = max(bv[j], bv[j - 1]);
            bv[j] = lo; bv[j - 1] = hi;
        }
    }

    // ---- edge weights + normalized gather (un-normalize via weight folding) ----
    const float alpha = e_a[0], beta = e_b[0];
    float wn[KNN]; int bi[KNN]; float wsum = 0.f;
    #pragma unroll
    for (int k = 0; k < KNN; ++k) {
        u32 key = bv[k];
        bi[k] = (int)(key & 255u);
        float sv = __uint_as_float((key >> 8) + 0x3F800000u) - 2.0f;
        float e = __expf(-(beta + alpha * sv));
        wn[k] = __fdividef(1.f, 1.f + e);
        wsum += wn[k];
    }
    const float inv = __fdividef(1.f, wsum + 1e-12f);

    u64 o2[8];
    #pragma unroll
    for (int j = 0; j < 8; ++j) o2[j] = 0ull;
    #pragma unroll
    for (int k = 0; k < KNN; ++k) {
        u64 ww = dup2(wn[k] * inv * nrm_s[bi[k]]);
        #pragma unroll
        for (int j2 = 0; j2 < 4; ++j2) {
            ulonglong2 q = nodes2[bi[k]][j2];
            o2[2 * j2]     = fma2(ww, q.x, o2[2 * j2]);
            o2[2 * j2 + 1] = fma2(ww, q.y, o2[2 * j2 + 1]);
        }
    }

    // duplicate gathered features into both lanes: g2[j] = (g[j], g[j])
    u64 g2[16];
    #pragma unroll
    for (int j = 0; j < 8; ++j) {
        float a, bb2; upk2(o2[j], a, bb2);
        g2[2 * j]     = dup2(a);
        g2[2 * j + 1] = dup2(bb2);
    }

    // ---- Phase 3: p conv (Cf=16 -> C=256), lanes = (co, co+1) per iteration ----
    const ulonglong2 (*w3)[4] = wbuf;   // view: element e = cp*8 + uu over u64x2
    float* op = out + (size_t)b * CC * HW
                    + (size_t)((wgi * 16 + wi) * 112 + wgj * 16 + hj);
    #pragma unroll 4
    for (int cp = 0; cp < 128; ++cp) {
        const ulonglong2* wr = &((const ulonglong2*)w3)[cp * 8];
        u64 acca = pb2_s[cp];   // bias pre-loaded into accumulator lanes
        u64 accb = 0ull;
        #pragma unroll
        for (int uu = 0; uu < 8; ++uu) {
            ulonglong2 q = wr[uu];
            acca = fma2(q.x, g2[2 * uu],     acca);
            accb = fma2(q.y, g2[2 * uu + 1], accb);
        }
        u64 r = add2(acca, accb);
        float r0, r1; upk2(r, r0, r1);
        op[(size_t)(2 * cp) * HW]     = r0;
        op[(size_t)(2 * cp + 1) * HW] = r1;
    }
}

extern "C" void kernel_launch(void* const* d_in, const int* in_sizes, int n_in,
                              void* d_out, int out_size) {
    const float* x   = (const float*)d_in[0];
    const float* f_w = (const float*)d_in[1];
    const float* f_b = (const float*)d_in[2];
    const float* p_w = (const float*)d_in[3];
    const float* p_b = (const float*)d_in[4];
    const float* e_a = (const float*)d_in[5];
    const float* e_b = (const float*)d_in[6];
    float* out = (float*)d_out;
    gnn_fused_kernel<<<784, 256>>>(x, f_w, f_b, p_w, p_b, e_a, e_b, out);
}

// round 3
// speedup vs baseline: 1.7022x; 1.0985x over previous
#include <cuda_runtime.h>

typedef unsigned long long u64;
typedef unsigned int u32;

__device__ __forceinline__ u64 pk2(float lo, float hi) {
    u64 r; asm("mov.b64 %0, {%1, %2};" : "=l"(r) : "f"(lo), "f"(hi)); return r;
}
__device__ __forceinline__ u64 dup2(float v) { return pk2(v, v); }
__device__ __forceinline__ void upk2(u64 v, float& a, float& b) {
    asm("mov.b64 {%0, %1}, %2;" : "=f"(a), "=f"(b) : "l"(v));
}
// Packed f32x2 ops (Blackwell) — 2x fp32 per issue slot.
__device__ __forceinline__ u64 fma2(u64 a, u64 b, u64 c) {
    u64 d; asm("fma.rn.f32x2 %0, %1, %2, %3;" : "=l"(d) : "l"(a), "l"(b), "l"(c)); return d;
}
__device__ __forceinline__ u64 add2(u64 a, u64 b) {
    u64 d; asm("add.rn.f32x2 %0, %1, %2;" : "=l"(d) : "l"(a), "l"(b)); return d;
}
__device__ __forceinline__ u64 mul2(u64 a, u64 b) {
    u64 d; asm("mul.rn.f32x2 %0, %1, %2;" : "=l"(d) : "l"(a), "l"(b)); return d;
}

#define KNN 9
#define CC 256      // channels
#define NN 256      // nodes per patch (16x16)
#define HW 12544    // 112*112

// 128 threads per block; thread t owns nodes t and t+128 of one 16x16 patch.
__global__ __launch_bounds__(128, 5) void gnn_fused_kernel(
    const float* __restrict__ x,
    const float* __restrict__ f_w, const float* __restrict__ f_b,
    const float* __restrict__ p_w, const float* __restrict__ p_b,
    const float* __restrict__ e_a, const float* __restrict__ e_b,
    float* __restrict__ out)
{
    // wbuf: phase 1 = fw2[c][j2] cf-pair packed f_w; phase 3 = raw p_w rows.
    __shared__ ulonglong2 wbuf[256][4];     // 16 KB
    __shared__ ulonglong2 nodes2[256][4];   // 16 KB: normalized node features
    __shared__ float nrm_s[256];
    __shared__ float pb_s[256];

    const int t   = threadIdx.x;           // 0..127
    const int blk = blockIdx.x;
    const int b   = blk / 49;
    const int rr  = blk % 49;
    const int wgi = rr / 7, wgj = rr % 7;
    const int wi  = t >> 4, hj = t & 15;    // node A = t (row wi), node B = t+128 (row wi+8)

    // ---- stage fw2[c][j] = (f_w[2j][c], f_w[2j+1][c]) : 2048 u64, 16/thread ----
    {
        u64* w = (u64*)wbuf;
        #pragma unroll
        for (int i = 0; i < 16; ++i) {
            int idx = i * 128 + t;
            int c = idx >> 3, j = idx & 7;
            w[idx] = pk2(f_w[(2 * j) * CC + c], f_w[(2 * j + 1) * CC + c]);
        }
    }
    pb_s[t] = p_b[t];
    pb_s[t + 128] = p_b[t + 128];

    u64 accA[8], accB[8];
    #pragma unroll
    for (int j = 0; j < 8; ++j) {
        u64 fb = pk2(f_b[2 * j], f_b[2 * j + 1]);
        accA[j] = fb; accB[j] = fb;
    }

    __syncthreads();

    // ---- Phase 1: f conv (C=256 -> Cf=16) for 2 pixels per thread ----
    const float* xpA = x + (size_t)b * CC * HW
                         + (size_t)((wgi * 16 + wi) * 112 + wgj * 16 + hj);
    const float* xpB = xpA + 8 * 112;
    #pragma unroll 1
    for (int c0 = 0; c0 < CC; c0 += 8) {
        float xa[8], xb[8];
        #pragma unroll
        for (int u = 0; u < 8; ++u) xa[u] = xpA[(size_t)u * HW];
        #pragma unroll
        for (int u = 0; u < 8; ++u) xb[u] = xpB[(size_t)u * HW];
        xpA += (size_t)8 * HW; xpB += (size_t)8 * HW;
        #pragma unroll
        for (int u = 0; u < 8; ++u) {
            u64 da = dup2(xa[u]);
            u64 db = dup2(xb[u]);
            #pragma unroll
            for (int j2 = 0; j2 < 4; ++j2) {
                ulonglong2 q = wbuf[c0 + u][j2];
                accA[2 * j2]     = fma2(da, q.x, accA[2 * j2]);
                accA[2 * j2 + 1] = fma2(da, q.y, accA[2 * j2 + 1]);
                accB[2 * j2]     = fma2(db, q.x, accB[2 * j2]);
                accB[2 * j2 + 1] = fma2(db, q.y, accB[2 * j2 + 1]);
            }
        }
    }

    // ---- normalize both nodes in registers ----
    {
        u64 sA = 0ull, sB = 0ull;
        #pragma unroll
        for (int j = 0; j < 8; ++j) { sA = fma2(accA[j], accA[j], sA); sB = fma2(accB[j], accB[j], sB); }
        float a0, a1, b0, b1; upk2(sA, a0, a1); upk2(sB, b0, b1);
        float ssA = a0 + a1, ssB = b0 + b1;
        nrm_s[t]       = sqrtf(ssA);
        nrm_s[t + 128] = sqrtf(ssB);
        u64 rA = dup2(rsqrtf(fmaxf(ssA, 1e-24f)));
        u64 rB = dup2(rsqrtf(fmaxf(ssB, 1e-24f)));
        #pragma unroll
        for (int j = 0; j < 8; ++j) { accA[j] = mul2(accA[j], rA); accB[j] = mul2(accB[j], rB); }
    }
    #pragma unroll
    for (int j2 = 0; j2 < 4; ++j2) {
        ulonglong2 qa; qa.x = accA[2 * j2]; qa.y = accA[2 * j2 + 1];
        ulonglong2 qb; qb.x = accB[2 * j2]; qb.y = accB[2 * j2 + 1];
        nodes2[t][j2] = qa;
        nodes2[t + 128][j2] = qb;
    }

    __syncthreads();   // phase-1 wbuf reads done; nodes2 visible

    // ---- restage wbuf with RAW p_w rows (layout already matches cf-pair lanes) ----
    {
        const float4* pw4 = (const float4*)p_w;   // 1024 float4
        float4* w4 = (float4*)wbuf;
        #pragma unroll
        for (int i = 0; i < 8; ++i) w4[i * 128 + t] = pw4[i * 128 + t];
    }
    __syncthreads();

    // ---- Phase 2: cosine sim + branch-free top-9 (packed u32 keys), 2 rows ----
    u32 bvA[KNN], bvB[KNN];
    #pragma unroll
    for (int k = 0; k < KNN; ++k) { bvA[k] = 0u; bvB[k] = 0u; }

    #pragma unroll 2
    for (int m = 0; m < NN; ++m) {
        ulonglong2 q0 = nodes2[m][0];
        ulonglong2 q1 = nodes2[m][1];
        ulonglong2 q2 = nodes2[m][2];
        ulonglong2 q3 = nodes2[m][3];
        u64 da = mul2(accA[0], q0.x), db = mul2(accA[1], q0.y);
        u64 ea = mul2(accB[0], q0.x), eb = mul2(accB[1], q0.y);
        da = fma2(accA[2], q1.x, da); db = fma2(accA[3], q1.y, db);
        ea = fma2(accB[2], q1.x, ea); eb = fma2(accB[3], q1.y, eb);
        da = fma2(accA[4], q2.x, da); db = fma2(accA[5], q2.y, db);
        ea = fma2(accB[4], q2.x, ea); eb = fma2(accB[5], q2.y, eb);
        da = fma2(accA[6], q3.x, da); db = fma2(accA[7], q3.y, db);
        ea = fma2(accB[6], q3.x, ea); eb = fma2(accB[7], q3.y, eb);
        u64 dA = add2(da, db);
        u64 dB = add2(ea, eb);
        float x0, x1, y0, y1; upk2(dA, x0, x1); upk2(dB, y0, y1);
        float dotA = x0 + x1, dotB = y0 + y1;
        u32 uA = __float_as_uint(fmaxf(dotA, -1.0f) + 2.0f) - 0x3F800000u;
        u32 uB = __float_as_uint(fmaxf(dotB, -1.0f) + 2.0f) - 0x3F800000u;
        u32 kA = uA * 256u + (u32)m;
        u32 kB = uB * 256u + (u32)m;
        bvA[KNN - 1] = max(bvA[KNN - 1], kA);
        bvB[KNN - 1] = max(bvB[KNN - 1], kB);
        #pragma unroll
        for (int j = KNN - 1; j > 0; --j) {
            u32 la = min(bvA[j], bvA[j - 1]);
            u32 ha = max(bvA[j], bvA[j - 1]);
            bvA[j] = la; bvA[j - 1] = ha;
            u32 lb = min(bvB[j], bvB[j - 1]);
            u32 hb = max(bvB[j], bvB[j - 1]);
            bvB[j] = lb; bvB[j - 1] = hb;
        }
    }

    // ---- edge weights + normalized gather, both nodes ----
    const float alpha = e_a[0], beta = e_b[0];
    u64 o2A[8], o2B[8];
    {
        float wnA[KNN], wnB[KNN]; int biA[KNN], biB[KNN];
        float wsA = 0.f, wsB = 0.f;
        #pragma unroll
        for (int k = 0; k < KNN; ++k) {
            biA[k] = (int)(bvA[k] & 255u);
            biB[k] = (int)(bvB[k] & 255u);
            float sA = __uint_as_float((bvA[k] >> 8) + 0x3F800000u) - 2.0f;
            float sB = __uint_as_float((bvB[k] >> 8) + 0x3F800000u) - 2.0f;
            wnA[k] = __fdividef(1.f, 1.f + __expf(-(beta + alpha * sA)));
            wnB[k] = __fdividef(1.f, 1.f + __expf(-(beta + alpha * sB)));
            wsA += wnA[k]; wsB += wnB[k];
        }
        const float ivA = __fdividef(1.f, wsA + 1e-12f);
        const float ivB = __fdividef(1.f, wsB + 1e-12f);
        #pragma unroll
        for (int j = 0; j < 8; ++j) { o2A[j] = 0ull; o2B[j] = 0ull; }
        #pragma unroll
        for (int k = 0; k < KNN; ++k) {
            u64 wA = dup2(wnA[k] * ivA * nrm_s[biA[k]]);
            u64 wB = dup2(wnB[k] * ivB * nrm_s[biB[k]]);
            #pragma unroll
            for (int j2 = 0; j2 < 4; ++j2) {
                ulonglong2 qa = nodes2[biA[k]][j2];
                ulonglong2 qb = nodes2[biB[k]][j2];
                o2A[2 * j2]     = fma2(wA, qa.x, o2A[2 * j2]);
                o2A[2 * j2 + 1] = fma2(wA, qa.y, o2A[2 * j2 + 1]);
                o2B[2 * j2]     = fma2(wB, qb.x, o2B[2 * j2]);
                o2B[2 * j2 + 1] = fma2(wB, qb.y, o2B[2 * j2 + 1]);
            }
        }
    }

    // ---- Phase 3: p conv (Cf=16 -> C=256), 2 pixels per thread ----
    float* opA = out + (size_t)b * CC * HW
                     + (size_t)((wgi * 16 + wi) * 112 + wgj * 16 + hj);
    float* opB = opA + 8 * 112;
    #pragma unroll 4
    for (int co = 0; co < CC; ++co) {
        ulonglong2 q0 = wbuf[co][0];
        ulonglong2 q1 = wbuf[co][1];
        ulonglong2 q2 = wbuf[co][2];
        ulonglong2 q3 = wbuf[co][3];
        u64 sa = mul2(q0.x, o2A[0]), sb = mul2(q0.y, o2A[1]);
        u64 ta = mul2(q0.x, o2B[0]), tb = mul2(q0.y, o2B[1]);
        sa = fma2(q1.x, o2A[2], sa); sb = fma2(q1.y, o2A[3], sb);
        ta = fma2(q1.x, o2B[2], ta); tb = fma2(q1.y, o2B[3], tb);
        sa = fma2(q2.x, o2A[4], sa); sb = fma2(q2.y, o2A[5], sb);
        ta = fma2(q2.x, o2B[4], ta); tb = fma2(q2.y, o2B[5], tb);
        sa = fma2(q3.x, o2A[6], sa); sb = fma2(q3.y, o2A[7], sb);
        ta = fma2(q3.x, o2B[6], ta); tb = fma2(q3.y, o2B[7], tb);
        u64 rA = add2(sa, sb);
        u64 rB = add2(ta, tb);
        float r0, r1, r2, r3; upk2(rA, r0, r1); upk2(rB, r2, r3);
        float pb = pb_s[co];
        opA[(size_t)co * HW] = (r0 + r1) + pb;
        opB[(size_t)co * HW] = (r2 + r3) + pb;
    }
}

extern "C" void kernel_launch(void* const* d_in, const int* in_sizes, int n_in,
                              void* d_out, int out_size) {
    const float* x   = (const float*)d_in[0];
    const float* f_w = (const float*)d_in[1];
    const float* f_b = (const float*)d_in[2];
    const float* p_w = (const float*)d_in[3];
    const float* p_b = (const float*)d_in[4];
    const float* e_a = (const float*)d_in[5];
    const float* e_b = (const float*)d_in[6];
    float* out = (float*)d_out;
    gnn_fused_kernel<<<784, 128>>>(x, f_w, f_b, p_w, p_b, e_a, e_b, out);
}